// round 3
// baseline (speedup 1.0000x reference)
#include <cuda_runtime.h>

#define NG 16
#define NBATCH 64
#define INV224 (1.0f / 224.0f)

static const int NA0 = 37632;   // 3*112*112
static const int NA1 = 9408;    // 3*56*56
static const int NA2 = 2352;    // 3*28*28
static const int NB0 = 147, NB1 = 37, NB2 = 10;

// scratch: [scale][image][anchor]
static __device__ float g_bce[3161088];
// per-(img,scale) 2048-bin histograms of float-bits>>20 (zero-init at load;
// phaseB re-zeroes after use so every replay starts clean)
static __device__ int   g_hist[192 * 2048];
static __device__ float g_posbce[192];
static __device__ float g_cls[192];
static __device__ float g_loc[192];
static __device__ int   g_npos[192];
static __device__ int   g_navail[192];
static __device__ float g_tot[3];
static __device__ int   g_done;

// ---------------- Phase A ----------------

template<int H, int NA, int ACCB, long SCRB>
__device__ __forceinline__ void phaseA_impl(const float* __restrict__ p,
                                            const float* __restrict__ anchors,
                                            const float* __restrict__ tb,
                                            const int*   __restrict__ tl,
                                            int bs, int b)
{
    constexpr int HH = H * H;
    __shared__ float stb[NG * 4];
    __shared__ int   stl[NG];
    __shared__ float s_pb, s_cl, s_lo;
    __shared__ int   s_np, s_nv;

    const int t = threadIdx.x;
    if (t < NG * 4) stb[t] = tb[b * NG * 4 + t] * INV224;
    if (t < NG)     stl[t] = tl[b * NG + t];
    if (t == 0) { s_pb = 0.f; s_cl = 0.f; s_lo = 0.f; s_np = 0; s_nv = 0; }
    __syncthreads();

    const int n = bs * 256 + t;
    bool pos = false, neg = false;

    if (n < NA) {
        const float4 a4 = ((const float4*)anchors)[n];
        const float ax1 = a4.x * INV224, ay1 = a4.y * INV224;
        const float ax2 = a4.z * INV224, ay2 = a4.w * INV224;
        const float aw = ax2 - ax1, ah = ay2 - ay1;
        const float area_a = aw * ah;

        // cross-multiplied argmax over IoU fractions (no division)
        float bestI = -1.0f, bestD = 1.0f; int bi = 0;
        #pragma unroll
        for (int g = 0; g < NG; g++) {
            float bx1 = stb[g * 4 + 0], by1 = stb[g * 4 + 1];
            float bx2 = stb[g * 4 + 2], by2 = stb[g * 4 + 3];
            float lx = fmaxf(ax1, bx1), ly = fmaxf(ay1, by1);
            float rx = fminf(ax2, bx2), ry = fminf(ay2, by2);
            float iw = fmaxf(rx - lx, 0.f), ih = fmaxf(ry - ly, 0.f);
            float inter = iw * ih;
            float den = area_a + (bx2 - bx1) * (by2 - by1) - inter + 1e-9f;
            if (inter * bestD > bestI * den) { bestI = inter; bestD = den; bi = g; }
        }
        pos = bestI >= 0.5f * bestD;
        neg = bestI < 0.4f * bestD;

        const int a = n / HH;
        const int rem = n - a * HH;
        const float* base = p + (((long)b * 3 + a) * 8) * (long)HH + rem;

        const float o = base[(long)4 * HH];
        const float objt = pos ? 1.f : 0.f;
        const float bce = fmaxf(o, 0.f) - o * objt + __logf(1.0f + __expf(-fabsf(o)));

        g_bce[SCRB + (long)b * NA + n] = neg ? bce : -1.0f;

        if (neg)
            atomicAdd(&g_hist[(ACCB + b) * 2048 + (int)(__float_as_uint(bce) >> 20)], 1);

        if (pos) {
            atomicAdd(&s_pb, bce);
            float mx1 = stb[bi * 4 + 0], my1 = stb[bi * 4 + 1];
            float mx2 = stb[bi * 4 + 2], my2 = stb[bi * 4 + 3];
            float gcx = 0.5f * (mx1 + mx2), gcy = 0.5f * (my1 + my2);
            float gw = mx2 - mx1, gh = my2 - my1;
            float acx = 0.5f * (ax1 + ax2), acy = 0.5f * (ay1 + ay2);
            float e0 = (gcx - acx) / aw;
            float e1 = (gcy - acy) / ah;
            float e2 = logf(gw / aw + 1e-6f);
            float e3 = logf(gh / ah + 1e-6f);
            float d0 = base[0]            - e0;
            float d1 = base[(long)1 * HH] - e1;
            float d2 = base[(long)2 * HH] - e2;
            float d3 = base[(long)3 * HH] - e3;
            #define SL1_(d) (fabsf(d) < 1.f ? 0.5f * (d) * (d) : fabsf(d) - 0.5f)
            atomicAdd(&s_lo, SL1_(d0) + SL1_(d1) + SL1_(d2) + SL1_(d3));
            #undef SL1_
            float z0 = base[(long)5 * HH];
            float z1 = base[(long)6 * HH];
            float z2 = base[(long)7 * HH];
            float m = fmaxf(z0, fmaxf(z1, z2));
            float lse = m + logf(expf(z0 - m) + expf(z1 - m) + expf(z2 - m));
            int ml = stl[bi];
            float zl = (ml == 1) ? z0 : ((ml == 2) ? z1 : z2);
            atomicAdd(&s_cl, lse - zl);
        }
    }

    unsigned nm = __ballot_sync(0xffffffff, neg);
    unsigned pm = __ballot_sync(0xffffffff, pos);
    if ((t & 31) == 0) {
        if (nm) atomicAdd(&s_nv, __popc(nm));
        if (pm) atomicAdd(&s_np, __popc(pm));
    }
    __syncthreads();
    if (t == 0) {
        const int acc = ACCB + b;
        if (s_np) {
            atomicAdd(&g_npos[acc],   s_np);
            atomicAdd(&g_posbce[acc], s_pb);
            atomicAdd(&g_cls[acc],    s_cl);
            atomicAdd(&g_loc[acc],    s_lo);
        }
        if (s_nv) atomicAdd(&g_navail[acc], s_nv);
    }
}

__global__ void __launch_bounds__(256) k_phaseA(const float* __restrict__ p0,
                                                const float* __restrict__ p1,
                                                const float* __restrict__ p2,
                                                const float* __restrict__ a0,
                                                const float* __restrict__ a1,
                                                const float* __restrict__ a2,
                                                const float* __restrict__ tb,
                                                const int*   __restrict__ tl)
{
    const int bx = blockIdx.x, b = blockIdx.y;
    if (bx < NB0)            phaseA_impl<112, NA0, 0,   0L>(p0, a0, tb, tl, bx, b);
    else if (bx < NB0 + NB1) phaseA_impl<56,  NA1, 64,  2408448L>(p1, a1, tb, tl, bx - NB0, b);
    else                     phaseA_impl<28,  NA2, 128, 3010560L>(p2, a2, tb, tl, bx - NB0 - NB1, b);
}

// ---------------- Phase B ----------------

// warp-shuffle based select of k-th-from-top over 1024 bins
__device__ __forceinline__ void select1024(const int* hist, int k, int t, int lane,
                                           int wid, int* s_w, int* sT, int* sKr)
{
    int c = hist[1023 - t];
    int v = c;
    #pragma unroll
    for (int o = 1; o < 32; o <<= 1) { int u = __shfl_up_sync(~0u, v, o); if (lane >= o) v += u; }
    if (lane == 31) s_w[wid] = v;
    __syncthreads();
    if (wid == 0) {
        int w = s_w[lane];
        #pragma unroll
        for (int o = 1; o < 32; o <<= 1) { int u = __shfl_up_sync(~0u, w, o); if (lane >= o) w += u; }
        s_w[lane] = w;
    }
    __syncthreads();
    int incl = v + (wid ? s_w[wid - 1] : 0);
    int excl = incl - c;
    if (excl < k && k <= incl) { *sT = 1023 - t; *sKr = k - excl; }
    __syncthreads();
}

__global__ void __launch_bounds__(1024) k_phaseB(float* __restrict__ out)
{
    const int idx = blockIdx.x;                 // 0..191
    const int scale = idx >> 6;
    const int b = idx & 63;
    const int Na   = (scale == 0) ? NA0 : ((scale == 1) ? NA1 : NA2);
    const long off = ((scale == 0) ? 0L : ((scale == 1) ? 2408448L : 3010560L)) + (long)b * Na;
    const int t = threadIdx.x, lane = t & 31, wid = t >> 5;
    const int npos = g_npos[idx];
    const int navail = g_navail[idx];

    __shared__ int   s_w[32];
    __shared__ float s_fw[32];
    __shared__ int   s_hist[1024];
    __shared__ float s_buf[4096];
    __shared__ int   s_cnt, sT, sKr;
    __shared__ float s_extra;

    int* hrow = &g_hist[idx * 2048];
    float partial = 0.f;
    float o_val = 0.f;
    const int k = min(3 * npos, navail);

    if (npos > 0 && navail > 0) {
        // --- level-1 select over 2048 bins (pairs from top), warp scans ---
        int c0 = hrow[2047 - 2 * t];
        int c1 = hrow[2046 - 2 * t];
        int v = c0 + c1;
        #pragma unroll
        for (int o = 1; o < 32; o <<= 1) { int u = __shfl_up_sync(~0u, v, o); if (lane >= o) v += u; }
        if (lane == 31) s_w[wid] = v;
        __syncthreads();
        if (wid == 0) {
            int w = s_w[lane];
            #pragma unroll
            for (int o = 1; o < 32; o <<= 1) { int u = __shfl_up_sync(~0u, w, o); if (lane >= o) w += u; }
            s_w[lane] = w;
        }
        if (t == 0) { s_cnt = 0; s_extra = 0.f; }
        __syncthreads();
        int incl = v + (wid ? s_w[wid - 1] : 0);
        int excl = incl - c0 - c1;
        if (excl < k && k <= incl) {
            if (excl + c0 >= k) { sT = 2047 - 2 * t; sKr = k - excl; }
            else                { sT = 2046 - 2 * t; sKr = k - excl - c0; }
        }
        __syncthreads();
        const int T = sT;
        int kr = sKr;
        const int cT = hrow[T];
        const bool fits = (cT <= 4096);

        // --- single float4 data scan: sum buckets > T, gather bucket T ---
        const float4* p4 = (const float4*)&g_bce[off];
        const int n4 = Na >> 2;
        for (int i = t; i < n4; i += 1024) {
            float4 q = p4[i];
            #pragma unroll
            for (int c = 0; c < 4; c++) {
                float x = (c == 0) ? q.x : (c == 1) ? q.y : (c == 2) ? q.z : q.w;
                unsigned u = __float_as_uint(x);
                if ((int)u >= 0) {
                    int bkt = (int)(u >> 20);
                    if (bkt > T) partial += x;
                    else if (bkt == T && fits) { int pb = atomicAdd(&s_cnt, 1); s_buf[pb] = x; }
                }
            }
        }
        __syncthreads();

        if (fits) {
            if (kr == cT) {
                for (int i = t; i < cT; i += 1024) partial += s_buf[i];
            } else {
                // brute-force exact top-kr among cT (<=4096) gathered values
                float m0 = (t        < cT) ? s_buf[t]        : -1.f;
                float m1 = (t + 1024 < cT) ? s_buf[t + 1024] : -1.f;
                float m2 = (t + 2048 < cT) ? s_buf[t + 2048] : -1.f;
                float m3 = (t + 3072 < cT) ? s_buf[t + 3072] : -1.f;
                int r0 = 0, r1 = 0, r2 = 0, r3 = 0;
                for (int i = 0; i < cT; i++) {
                    float x = s_buf[i];
                    r0 += (x > m0) || (x == m0 && i < t);
                    r1 += (x > m1) || (x == m1 && i < t + 1024);
                    r2 += (x > m2) || (x == m2 && i < t + 2048);
                    r3 += (x > m3) || (x == m3 && i < t + 3072);
                }
                if (t        < cT && r0 < kr) partial += m0;
                if (t + 1024 < cT && r1 < kr) partial += m1;
                if (t + 2048 < cT && r2 < kr) partial += m2;
                if (t + 3072 < cT && r3 < kr) partial += m3;
            }
        } else {
            // rare fallback: radix refine via global rescans, then exact sum
            s_hist[t] = 0;
            __syncthreads();
            for (int i = t; i < Na; i += 1024) {
                unsigned u = __float_as_uint(g_bce[off + i]);
                if ((int)u >= 0 && (int)(u >> 20) == T)
                    atomicAdd(&s_hist[(u >> 10) & 1023], 1);
            }
            __syncthreads();
            select1024(s_hist, kr, t, lane, wid, s_w, &sT, &sKr);
            const int T2 = sT; kr = sKr;
            __syncthreads();
            s_hist[t] = 0;
            __syncthreads();
            const unsigned top22 = ((unsigned)T << 10) | (unsigned)T2;
            for (int i = t; i < Na; i += 1024) {
                unsigned u = __float_as_uint(g_bce[off + i]);
                if ((int)u >= 0 && (u >> 10) == top22)
                    atomicAdd(&s_hist[u & 1023], 1);
            }
            __syncthreads();
            select1024(s_hist, kr, t, lane, wid, s_w, &sT, &sKr);
            const unsigned thrbits = ((unsigned)T << 20) | ((unsigned)T2 << 10) | (unsigned)sT;
            const int krf = sKr;
            __syncthreads();
            partial = 0.f;
            for (int i = t; i < Na; i += 1024) {
                float x = g_bce[off + i];
                unsigned u = __float_as_uint(x);
                if ((int)u >= 0 && u > thrbits) partial += x;
            }
            if (t == 0) s_extra = (float)krf * __uint_as_float(thrbits);
        }

        // --- block reduce of partial ---
        #pragma unroll
        for (int o = 16; o; o >>= 1) partial += __shfl_down_sync(~0u, partial, o);
        if (lane == 0) s_fw[wid] = partial;
        __syncthreads();
        if (t == 0) {
            float s = s_extra;
            #pragma unroll
            for (int i = 0; i < 32; i++) s += s_fw[i];
            o_val = g_posbce[idx] / (float)npos + s / (float)k;
        }
    }

    // --- cleanup for next replay + accumulate totals ---
    hrow[t] = 0;
    hrow[t + 1024] = 0;
    if (t == 0) {
        float c = 0.f, l = 0.f;
        if (npos > 0) {
            c = g_cls[idx] / (float)npos;
            l = g_loc[idx] / (4.0f * (float)npos);
        }
        g_npos[idx] = 0; g_navail[idx] = 0;
        g_posbce[idx] = 0.f; g_cls[idx] = 0.f; g_loc[idx] = 0.f;
        atomicAdd(&g_tot[0], o_val);
        atomicAdd(&g_tot[1], c);
        atomicAdd(&g_tot[2], l);
        __threadfence();
        int done = atomicAdd(&g_done, 1);
        if (done == 191) {
            __threadfence();
            float oo = g_tot[0] / (float)NBATCH;
            float cc = g_tot[1] / (float)NBATCH;
            float ll = g_tot[2] / (float)NBATCH;
            out[0] = oo; out[1] = cc; out[2] = ll; out[3] = oo + cc + ll;
            g_tot[0] = 0.f; g_tot[1] = 0.f; g_tot[2] = 0.f;
            g_done = 0;
        }
    }
}

extern "C" void kernel_launch(void* const* d_in, const int* in_sizes, int n_in,
                              void* d_out, int out_size)
{
    const float* p0 = (const float*)d_in[0];
    const float* p1 = (const float*)d_in[1];
    const float* p2 = (const float*)d_in[2];
    const float* a0 = (const float*)d_in[3];
    const float* a1 = (const float*)d_in[4];
    const float* a2 = (const float*)d_in[5];
    const float* tb = (const float*)d_in[6];
    const int*   tl = (const int*)  d_in[7];

    dim3 gA(NB0 + NB1 + NB2, NBATCH);
    k_phaseA<<<gA, 256>>>(p0, p1, p2, a0, a1, a2, tb, tl);
    k_phaseB<<<192, 1024>>>((float*)d_out);
}

// round 4
// speedup vs baseline: 1.6752x; 1.6752x over previous
#include <cuda_runtime.h>

#define NG 16
#define NBATCH 64
#define INV224 (1.0f / 224.0f)

static const int NA0 = 37632;   // 3*112*112
static const int NA1 = 9408;    // 3*56*56
static const int NA2 = 2352;    // 3*28*28
static const int NB0 = 147, NB1 = 37, NB2 = 10;

// scratch: [scale][image][anchor]
static __device__ float g_bce[3161088];
// per-(img,scale) 2048-bin histograms of float-bits>>20 (phaseB re-zeroes)
static __device__ int   g_hist[192 * 2048];
static __device__ float g_posbce[192];
static __device__ float g_cls[192];
static __device__ float g_loc[192];
static __device__ int   g_npos[192];
static __device__ int   g_navail[192];
static __device__ float g_tot[3];
static __device__ int   g_done;

// ---------------- Phase A ----------------

template<int H, int NA, int ACCB, long SCRB>
__device__ __forceinline__ void phaseA_impl(const float* __restrict__ p,
                                            const float* __restrict__ anchors,
                                            const float* __restrict__ tb,
                                            const int*   __restrict__ tl,
                                            int bs, int b)
{
    constexpr int HH = H * H;
    __shared__ float stb[NG * 4];
    __shared__ float sarea[NG];
    __shared__ int   stl[NG];
    __shared__ float s_pb, s_cl, s_lo;
    __shared__ int   s_np, s_nv;

    const int t = threadIdx.x;
    if (t < NG * 4) stb[t] = tb[b * NG * 4 + t] * INV224;
    if (t < NG)     stl[t] = tl[b * NG + t];
    if (t == 0) { s_pb = 0.f; s_cl = 0.f; s_lo = 0.f; s_np = 0; s_nv = 0; }
    __syncthreads();
    if (t < NG) sarea[t] = (stb[t * 4 + 2] - stb[t * 4 + 0]) * (stb[t * 4 + 3] - stb[t * 4 + 1]);
    __syncthreads();

    const int n = bs * 256 + t;
    bool pos = false, neg = false;

    if (n < NA) {
        const float4 a4 = ((const float4*)anchors)[n];
        const float ax1 = a4.x * INV224, ay1 = a4.y * INV224;
        const float ax2 = a4.z * INV224, ay2 = a4.w * INV224;
        const float aw = ax2 - ax1, ah = ay2 - ay1;
        const float area_a = aw * ah;

        float bestI = -1.0f, bestD = 1.0f; int bi = 0;
        #pragma unroll
        for (int g = 0; g < NG; g++) {
            float lx = fmaxf(ax1, stb[g * 4 + 0]);
            float ly = fmaxf(ay1, stb[g * 4 + 1]);
            float rx = fminf(ax2, stb[g * 4 + 2]);
            float ry = fminf(ay2, stb[g * 4 + 3]);
            float iw = fmaxf(rx - lx, 0.f), ih = fmaxf(ry - ly, 0.f);
            float inter = iw * ih;
            float den = area_a + sarea[g] - inter + 1e-9f;
            if (inter * bestD > bestI * den) { bestI = inter; bestD = den; bi = g; }
        }
        pos = bestI >= 0.5f * bestD;
        neg = bestI < 0.4f * bestD;

        const int a = n / HH;
        const int rem = n - a * HH;
        const float* base = p + (((long)b * 3 + a) * 8) * (long)HH + rem;

        const float o = base[(long)4 * HH];
        const float objt = pos ? 1.f : 0.f;
        const float bce = fmaxf(o, 0.f) - o * objt + __logf(1.0f + __expf(-fabsf(o)));

        g_bce[SCRB + (long)b * NA + n] = neg ? bce : -1.0f;

        if (neg)
            atomicAdd(&g_hist[(ACCB + b) * 2048 + (int)(__float_as_uint(bce) >> 20)], 1);

        if (pos) {
            atomicAdd(&s_pb, bce);
            float mx1 = stb[bi * 4 + 0], my1 = stb[bi * 4 + 1];
            float mx2 = stb[bi * 4 + 2], my2 = stb[bi * 4 + 3];
            float gcx = 0.5f * (mx1 + mx2), gcy = 0.5f * (my1 + my2);
            float gw = mx2 - mx1, gh = my2 - my1;
            float acx = 0.5f * (ax1 + ax2), acy = 0.5f * (ay1 + ay2);
            float e0 = (gcx - acx) / aw;
            float e1 = (gcy - acy) / ah;
            float e2 = logf(gw / aw + 1e-6f);
            float e3 = logf(gh / ah + 1e-6f);
            float d0 = base[0]            - e0;
            float d1 = base[(long)1 * HH] - e1;
            float d2 = base[(long)2 * HH] - e2;
            float d3 = base[(long)3 * HH] - e3;
            #define SL1_(d) (fabsf(d) < 1.f ? 0.5f * (d) * (d) : fabsf(d) - 0.5f)
            atomicAdd(&s_lo, SL1_(d0) + SL1_(d1) + SL1_(d2) + SL1_(d3));
            #undef SL1_
            float z0 = base[(long)5 * HH];
            float z1 = base[(long)6 * HH];
            float z2 = base[(long)7 * HH];
            float m = fmaxf(z0, fmaxf(z1, z2));
            float lse = m + logf(expf(z0 - m) + expf(z1 - m) + expf(z2 - m));
            int ml = stl[bi];
            float zl = (ml == 1) ? z0 : ((ml == 2) ? z1 : z2);
            atomicAdd(&s_cl, lse - zl);
        }
    }

    unsigned nm = __ballot_sync(0xffffffff, neg);
    unsigned pm = __ballot_sync(0xffffffff, pos);
    if ((t & 31) == 0) {
        if (nm) atomicAdd(&s_nv, __popc(nm));
        if (pm) atomicAdd(&s_np, __popc(pm));
    }
    __syncthreads();
    if (t == 0) {
        const int acc = ACCB + b;
        if (s_np) {
            atomicAdd(&g_npos[acc],   s_np);
            atomicAdd(&g_posbce[acc], s_pb);
            atomicAdd(&g_cls[acc],    s_cl);
            atomicAdd(&g_loc[acc],    s_lo);
        }
        if (s_nv) atomicAdd(&g_navail[acc], s_nv);
    }
}

__global__ void __launch_bounds__(256) k_phaseA(const float* __restrict__ p0,
                                                const float* __restrict__ p1,
                                                const float* __restrict__ p2,
                                                const float* __restrict__ a0,
                                                const float* __restrict__ a1,
                                                const float* __restrict__ a2,
                                                const float* __restrict__ tb,
                                                const int*   __restrict__ tl)
{
    const int bx = blockIdx.x, b = blockIdx.y;
    if (bx < NB0)            phaseA_impl<112, NA0, 0,   0L>(p0, a0, tb, tl, bx, b);
    else if (bx < NB0 + NB1) phaseA_impl<56,  NA1, 64,  2408448L>(p1, a1, tb, tl, bx - NB0, b);
    else                     phaseA_impl<28,  NA2, 128, 3010560L>(p2, a2, tb, tl, bx - NB0 - NB1, b);
}

// ---------------- Phase B ----------------

// warp-shuffle based select of k-th-from-top over 1024 bins
__device__ __forceinline__ void select1024(const int* hist, int k, int t, int lane,
                                           int wid, int* s_w, int* sT, int* sKr)
{
    int c = hist[1023 - t];
    int v = c;
    #pragma unroll
    for (int o = 1; o < 32; o <<= 1) { int u = __shfl_up_sync(~0u, v, o); if (lane >= o) v += u; }
    if (lane == 31) s_w[wid] = v;
    __syncthreads();
    if (wid == 0) {
        int w = s_w[lane];
        #pragma unroll
        for (int o = 1; o < 32; o <<= 1) { int u = __shfl_up_sync(~0u, w, o); if (lane >= o) w += u; }
        s_w[lane] = w;
    }
    __syncthreads();
    int incl = v + (wid ? s_w[wid - 1] : 0);
    int excl = incl - c;
    if (excl < k && k <= incl) { *sT = 1023 - t; *sKr = k - excl; }
    __syncthreads();
}

__global__ void __launch_bounds__(1024) k_phaseB(float* __restrict__ out)
{
    const int idx = blockIdx.x;                 // 0..191
    const int scale = idx >> 6;
    const int b = idx & 63;
    const int Na   = (scale == 0) ? NA0 : ((scale == 1) ? NA1 : NA2);
    const long off = ((scale == 0) ? 0L : ((scale == 1) ? 2408448L : 3010560L)) + (long)b * Na;
    const int t = threadIdx.x, lane = t & 31, wid = t >> 5;
    const int npos = g_npos[idx];
    const int navail = g_navail[idx];

    __shared__ int   s_w[32];
    __shared__ float s_fw[32];
    __shared__ int   s_hist[1024];
    __shared__ float s_buf[4096];
    __shared__ int   s_cnt, sT, sKr;
    __shared__ float s_extra;

    int* hrow = &g_hist[idx * 2048];
    float partial = 0.f;
    float o_val = 0.f;
    const int k = min(3 * npos, navail);

    if (npos > 0 && navail > 0) {
        // --- level-1 select over 2048 bins (pairs from top), warp scans ---
        int c0 = hrow[2047 - 2 * t];
        int c1 = hrow[2046 - 2 * t];
        int v = c0 + c1;
        #pragma unroll
        for (int o = 1; o < 32; o <<= 1) { int u = __shfl_up_sync(~0u, v, o); if (lane >= o) v += u; }
        if (lane == 31) s_w[wid] = v;
        __syncthreads();
        if (wid == 0) {
            int w = s_w[lane];
            #pragma unroll
            for (int o = 1; o < 32; o <<= 1) { int u = __shfl_up_sync(~0u, w, o); if (lane >= o) w += u; }
            s_w[lane] = w;
        }
        if (t == 0) { s_cnt = 0; s_extra = 0.f; }
        __syncthreads();
        int incl = v + (wid ? s_w[wid - 1] : 0);
        int excl = incl - c0 - c1;
        if (excl < k && k <= incl) {
            if (excl + c0 >= k) { sT = 2047 - 2 * t; sKr = k - excl; }
            else                { sT = 2046 - 2 * t; sKr = k - excl - c0; }
        }
        __syncthreads();
        const int T = sT;
        int kr = sKr;
        const int cT = hrow[T];
        const bool fits = (cT <= 4096);

        // --- single float4 data scan: sum buckets > T, gather bucket T ---
        const float4* p4 = (const float4*)&g_bce[off];
        const int n4 = Na >> 2;
        for (int i = t; i < n4; i += 1024) {
            float4 q = p4[i];
            #pragma unroll
            for (int c = 0; c < 4; c++) {
                float x = (c == 0) ? q.x : (c == 1) ? q.y : (c == 2) ? q.z : q.w;
                unsigned u = __float_as_uint(x);
                if ((int)u >= 0) {
                    int bkt = (int)(u >> 20);
                    if (bkt > T) partial += x;
                    else if (bkt == T && fits) { int pb = atomicAdd(&s_cnt, 1); s_buf[pb] = x; }
                }
            }
        }
        __syncthreads();

        if (fits) {
            if (kr == cT) {
                // whole bucket selected
                for (int i = t; i < cT; i += 1024) partial += s_buf[i];
            } else {
                // radix refinement on the gathered bucket (smem resident)
                // level-2: bits[19:10]
                s_hist[t] = 0;
                __syncthreads();
                for (int i = t; i < cT; i += 1024)
                    atomicAdd(&s_hist[(__float_as_uint(s_buf[i]) >> 10) & 1023], 1);
                __syncthreads();
                select1024(s_hist, kr, t, lane, wid, s_w, &sT, &sKr);
                const int T2 = sT; kr = sKr;
                __syncthreads();
                // level-3: bits[9:0]
                s_hist[t] = 0;
                __syncthreads();
                for (int i = t; i < cT; i += 1024) {
                    unsigned u = __float_as_uint(s_buf[i]);
                    if (((u >> 10) & 1023) == (unsigned)T2) atomicAdd(&s_hist[u & 1023], 1);
                }
                __syncthreads();
                select1024(s_hist, kr, t, lane, wid, s_w, &sT, &sKr);
                const unsigned thrbits = ((unsigned)T << 20) | ((unsigned)T2 << 10) | (unsigned)sT;
                const int krf = sKr;
                __syncthreads();
                for (int i = t; i < cT; i += 1024) {
                    float x = s_buf[i];
                    if (__float_as_uint(x) > thrbits) partial += x;
                }
                if (t == 0) s_extra = (float)krf * __uint_as_float(thrbits);
            }
        } else {
            // rare fallback: refine via global rescans, then exact sum
            s_hist[t] = 0;
            __syncthreads();
            for (int i = t; i < Na; i += 1024) {
                unsigned u = __float_as_uint(g_bce[off + i]);
                if ((int)u >= 0 && (int)(u >> 20) == T)
                    atomicAdd(&s_hist[(u >> 10) & 1023], 1);
            }
            __syncthreads();
            select1024(s_hist, kr, t, lane, wid, s_w, &sT, &sKr);
            const int T2 = sT; kr = sKr;
            __syncthreads();
            s_hist[t] = 0;
            __syncthreads();
            const unsigned top22 = ((unsigned)T << 10) | (unsigned)T2;
            for (int i = t; i < Na; i += 1024) {
                unsigned u = __float_as_uint(g_bce[off + i]);
                if ((int)u >= 0 && (u >> 10) == top22)
                    atomicAdd(&s_hist[u & 1023], 1);
            }
            __syncthreads();
            select1024(s_hist, kr, t, lane, wid, s_w, &sT, &sKr);
            const unsigned thrbits = ((unsigned)T << 20) | ((unsigned)T2 << 10) | (unsigned)sT;
            const int krf = sKr;
            __syncthreads();
            partial = 0.f;
            for (int i = t; i < Na; i += 1024) {
                float x = g_bce[off + i];
                unsigned u = __float_as_uint(x);
                if ((int)u >= 0 && u > thrbits) partial += x;
            }
            if (t == 0) s_extra = (float)krf * __uint_as_float(thrbits);
        }

        // --- block reduce of partial ---
        #pragma unroll
        for (int o = 16; o; o >>= 1) partial += __shfl_down_sync(~0u, partial, o);
        if (lane == 0) s_fw[wid] = partial;
        __syncthreads();
        if (t == 0) {
            float s = s_extra;
            #pragma unroll
            for (int i = 0; i < 32; i++) s += s_fw[i];
            o_val = g_posbce[idx] / (float)npos + s / (float)k;
        }
    }

    // --- cleanup for next replay + accumulate totals ---
    hrow[t] = 0;
    hrow[t + 1024] = 0;
    if (t == 0) {
        float c = 0.f, l = 0.f;
        if (npos > 0) {
            c = g_cls[idx] / (float)npos;
            l = g_loc[idx] / (4.0f * (float)npos);
        }
        g_npos[idx] = 0; g_navail[idx] = 0;
        g_posbce[idx] = 0.f; g_cls[idx] = 0.f; g_loc[idx] = 0.f;
        atomicAdd(&g_tot[0], o_val);
        atomicAdd(&g_tot[1], c);
        atomicAdd(&g_tot[2], l);
        __threadfence();
        int done = atomicAdd(&g_done, 1);
        if (done == 191) {
            __threadfence();
            float oo = g_tot[0] / (float)NBATCH;
            float cc = g_tot[1] / (float)NBATCH;
            float ll = g_tot[2] / (float)NBATCH;
            out[0] = oo; out[1] = cc; out[2] = ll; out[3] = oo + cc + ll;
            g_tot[0] = 0.f; g_tot[1] = 0.f; g_tot[2] = 0.f;
            g_done = 0;
        }
    }
}

extern "C" void kernel_launch(void* const* d_in, const int* in_sizes, int n_in,
                              void* d_out, int out_size)
{
    const float* p0 = (const float*)d_in[0];
    const float* p1 = (const float*)d_in[1];
    const float* p2 = (const float*)d_in[2];
    const float* a0 = (const float*)d_in[3];
    const float* a1 = (const float*)d_in[4];
    const float* a2 = (const float*)d_in[5];
    const float* tb = (const float*)d_in[6];
    const int*   tl = (const int*)  d_in[7];

    dim3 gA(NB0 + NB1 + NB2, NBATCH);
    k_phaseA<<<gA, 256>>>(p0, p1, p2, a0, a1, a2, tb, tl);
    k_phaseB<<<192, 1024>>>((float*)d_out);
}

// round 6
// speedup vs baseline: 1.7610x; 1.0513x over previous
#include <cuda_runtime.h>

#define NG 16
#define NBATCH 64
#define INV224 (1.0f / 224.0f)

static const int NA0 = 37632;   // 3*112*112
static const int NA1 = 9408;    // 3*56*56
static const int NA2 = 2352;    // 3*28*28
// phaseA blocks process 1024 anchors each (256 thr x 4)
static const int NBa0 = 37, NBa1 = 10, NBa2 = 3;

// scratch: [scale][image][anchor]
static __device__ float g_bce[3161088];
// per-(img,scale) 2048-bin histograms of float-bits>>20 (phaseB re-zeroes)
static __device__ int   g_hist[192 * 2048];
static __device__ float g_posbce[192];
static __device__ float g_cls[192];
static __device__ float g_loc[192];
static __device__ int   g_npos[192];
static __device__ int   g_navail[192];
static __device__ float g_tot[3];
static __device__ int   g_done;

// ---------------- Phase A ----------------

template<int H, int NA, int ACCB, long SCRB>
__device__ __forceinline__ void phaseA_impl(const float* __restrict__ p,
                                            const float* __restrict__ anchors,
                                            const float* __restrict__ tb,
                                            const int*   __restrict__ tl,
                                            int bs, int b)
{
    constexpr int HH = H * H;
    __shared__ float stb[NG * 4];
    __shared__ float sarea[NG];
    __shared__ int   stl[NG];
    __shared__ float s_pb, s_cl, s_lo;
    __shared__ int   s_np, s_nv;

    const int t = threadIdx.x;
    if (t < NG * 4) stb[t] = tb[b * NG * 4 + t] * INV224;
    if (t < NG)     stl[t] = tl[b * NG + t];
    if (t == 0) { s_pb = 0.f; s_cl = 0.f; s_lo = 0.f; s_np = 0; s_nv = 0; }
    __syncthreads();
    if (t < NG) sarea[t] = (stb[t * 4 + 2] - stb[t * 4 + 0]) * (stb[t * 4 + 3] - stb[t * 4 + 1]);
    __syncthreads();

    const int n0 = bs * 1024 + t;

    float ax1[4], ay1[4], ax2[4], ay2[4], area[4];
    bool  act[4];
    #pragma unroll
    for (int j = 0; j < 4; j++) {
        const int n = n0 + j * 256;
        act[j] = (n < NA);
        if (act[j]) {
            const float4 a4 = ((const float4*)anchors)[n];
            ax1[j] = a4.x * INV224; ay1[j] = a4.y * INV224;
            ax2[j] = a4.z * INV224; ay2[j] = a4.w * INV224;
            area[j] = (ax2[j] - ax1[j]) * (ay2[j] - ay1[j]);
        } else {
            ax1[j] = 0.f; ay1[j] = 0.f; ax2[j] = 0.f; ay2[j] = 0.f; area[j] = 0.f;
        }
    }

    float bestI[4], bestD[4]; int bi[4];
    #pragma unroll
    for (int j = 0; j < 4; j++) { bestI[j] = -1.f; bestD[j] = 1.f; bi[j] = 0; }

    // 16-box IoU loop: smem loads amortized across the 4 anchors
    #pragma unroll
    for (int g = 0; g < NG; g++) {
        const float bx1 = stb[g * 4 + 0], by1 = stb[g * 4 + 1];
        const float bx2 = stb[g * 4 + 2], by2 = stb[g * 4 + 3];
        const float ba  = sarea[g];
        #pragma unroll
        for (int j = 0; j < 4; j++) {
            float lx = fmaxf(ax1[j], bx1), ly = fmaxf(ay1[j], by1);
            float rx = fminf(ax2[j], bx2), ry = fminf(ay2[j], by2);
            float iw = fmaxf(rx - lx, 0.f), ih = fmaxf(ry - ly, 0.f);
            float inter = iw * ih;
            float den = area[j] + ba - inter + 1e-9f;
            if (inter * bestD[j] > bestI[j] * den) { bestI[j] = inter; bestD[j] = den; bi[j] = g; }
        }
    }

    #pragma unroll
    for (int j = 0; j < 4; j++) {
        const int n = n0 + j * 256;
        bool pos = false, neg = false;
        if (act[j]) {
            pos = bestI[j] >= 0.5f * bestD[j];
            neg = bestI[j] <  0.4f * bestD[j];

            const int a = n / HH;
            const int rem = n - a * HH;
            const float* base = p + (((long)b * 3 + a) * 8) * (long)HH + rem;

            const float o = base[(long)4 * HH];
            const float bce = fmaxf(o, 0.f) - (pos ? o : 0.f) + __logf(1.0f + __expf(-fabsf(o)));

            g_bce[SCRB + (long)b * NA + n] = neg ? bce : -1.0f;

            if (neg)
                atomicAdd(&g_hist[(ACCB + b) * 2048 + (int)(__float_as_uint(bce) >> 20)], 1);

            if (pos) {
                atomicAdd(&s_pb, bce);
                const int gi = bi[j];
                float mx1 = stb[gi * 4 + 0], my1 = stb[gi * 4 + 1];
                float mx2 = stb[gi * 4 + 2], my2 = stb[gi * 4 + 3];
                float gcx = 0.5f * (mx1 + mx2), gcy = 0.5f * (my1 + my2);
                float gw = mx2 - mx1, gh = my2 - my1;
                float aw = ax2[j] - ax1[j], ah = ay2[j] - ay1[j];
                float acx = 0.5f * (ax1[j] + ax2[j]), acy = 0.5f * (ay1[j] + ay2[j]);
                float e0 = __fdividef(gcx - acx, aw);
                float e1 = __fdividef(gcy - acy, ah);
                float e2 = __logf(__fdividef(gw, aw) + 1e-6f);
                float e3 = __logf(__fdividef(gh, ah) + 1e-6f);
                float d0 = base[0]            - e0;
                float d1 = base[(long)1 * HH] - e1;
                float d2 = base[(long)2 * HH] - e2;
                float d3 = base[(long)3 * HH] - e3;
                #define SL1_(d) (fabsf(d) < 1.f ? 0.5f * (d) * (d) : fabsf(d) - 0.5f)
                atomicAdd(&s_lo, SL1_(d0) + SL1_(d1) + SL1_(d2) + SL1_(d3));
                #undef SL1_
                float z0 = base[(long)5 * HH];
                float z1 = base[(long)6 * HH];
                float z2 = base[(long)7 * HH];
                float m = fmaxf(z0, fmaxf(z1, z2));
                float lse = m + __logf(__expf(z0 - m) + __expf(z1 - m) + __expf(z2 - m));
                int ml = stl[gi];
                float zl = (ml == 1) ? z0 : ((ml == 2) ? z1 : z2);
                atomicAdd(&s_cl, lse - zl);
            }
        }
        unsigned nm = __ballot_sync(0xffffffff, neg);
        unsigned pm = __ballot_sync(0xffffffff, pos);
        if ((t & 31) == 0) {
            if (nm) atomicAdd(&s_nv, __popc(nm));
            if (pm) atomicAdd(&s_np, __popc(pm));
        }
    }

    __syncthreads();
    if (t == 0) {
        const int acc = ACCB + b;
        if (s_np) {
            atomicAdd(&g_npos[acc],   s_np);
            atomicAdd(&g_posbce[acc], s_pb);
            atomicAdd(&g_cls[acc],    s_cl);
            atomicAdd(&g_loc[acc],    s_lo);
        }
        if (s_nv) atomicAdd(&g_navail[acc], s_nv);
    }
}

__global__ void __launch_bounds__(256) k_phaseA(const float* __restrict__ p0,
                                                const float* __restrict__ p1,
                                                const float* __restrict__ p2,
                                                const float* __restrict__ a0,
                                                const float* __restrict__ a1,
                                                const float* __restrict__ a2,
                                                const float* __restrict__ tb,
                                                const int*   __restrict__ tl)
{
    const int bx = blockIdx.x, b = blockIdx.y;
    if (bx < NBa0)             phaseA_impl<112, NA0, 0,   0L>(p0, a0, tb, tl, bx, b);
    else if (bx < NBa0 + NBa1) phaseA_impl<56,  NA1, 64,  2408448L>(p1, a1, tb, tl, bx - NBa0, b);
    else                       phaseA_impl<28,  NA2, 128, 3010560L>(p2, a2, tb, tl, bx - NBa0 - NBa1, b);
}

// ---------------- Phase B ----------------

__device__ __forceinline__ void select1024(const int* hist, int k, int t, int lane,
                                           int wid, int* s_w, int* sT, int* sKr)
{
    int c = hist[1023 - t];
    int v = c;
    #pragma unroll
    for (int o = 1; o < 32; o <<= 1) { int u = __shfl_up_sync(~0u, v, o); if (lane >= o) v += u; }
    if (lane == 31) s_w[wid] = v;
    __syncthreads();
    if (wid == 0) {
        int w = s_w[lane];
        #pragma unroll
        for (int o = 1; o < 32; o <<= 1) { int u = __shfl_up_sync(~0u, w, o); if (lane >= o) w += u; }
        s_w[lane] = w;
    }
    __syncthreads();
    int incl = v + (wid ? s_w[wid - 1] : 0);
    int excl = incl - c;
    if (excl < k && k <= incl) { *sT = 1023 - t; *sKr = k - excl; }
    __syncthreads();
}

__global__ void __launch_bounds__(1024) k_phaseB(float* __restrict__ out)
{
    const int idx = blockIdx.x;                 // 0..191
    const int scale = idx >> 6;
    const int b = idx & 63;
    const int Na   = (scale == 0) ? NA0 : ((scale == 1) ? NA1 : NA2);
    const long off = ((scale == 0) ? 0L : ((scale == 1) ? 2408448L : 3010560L)) + (long)b * Na;
    const int t = threadIdx.x, lane = t & 31, wid = t >> 5;
    const int npos = g_npos[idx];
    const int navail = g_navail[idx];

    __shared__ int   s_w[32];
    __shared__ float s_fw[32];
    __shared__ int   s_hist[1024];
    __shared__ float s_buf[4096];
    __shared__ int   s_cnt, sT, sKr;
    __shared__ float s_extra;

    int* hrow = &g_hist[idx * 2048];
    float partial = 0.f;
    float o_val = 0.f;
    const int k = min(3 * npos, navail);

    if (npos > 0 && navail > 0) {
        // --- level-1 select over 2048 bins (pairs from top), warp scans ---
        int c0 = hrow[2047 - 2 * t];
        int c1 = hrow[2046 - 2 * t];
        int v = c0 + c1;
        #pragma unroll
        for (int o = 1; o < 32; o <<= 1) { int u = __shfl_up_sync(~0u, v, o); if (lane >= o) v += u; }
        if (lane == 31) s_w[wid] = v;
        __syncthreads();
        if (wid == 0) {
            int w = s_w[lane];
            #pragma unroll
            for (int o = 1; o < 32; o <<= 1) { int u = __shfl_up_sync(~0u, w, o); if (lane >= o) w += u; }
            s_w[lane] = w;
        }
        if (t == 0) { s_cnt = 0; s_extra = 0.f; }
        __syncthreads();
        int incl = v + (wid ? s_w[wid - 1] : 0);
        int excl = incl - c0 - c1;
        if (excl < k && k <= incl) {
            if (excl + c0 >= k) { sT = 2047 - 2 * t; sKr = k - excl; }
            else                { sT = 2046 - 2 * t; sKr = k - excl - c0; }
        }
        __syncthreads();
        const int T = sT;
        int kr = sKr;
        const int cT = hrow[T];
        const bool fits = (cT <= 4096);

        // --- single float4 data scan: sum buckets > T, gather bucket T ---
        const float4* p4 = (const float4*)&g_bce[off];
        const int n4 = Na >> 2;
        for (int i = t; i < n4; i += 1024) {
            float4 q = p4[i];
            #pragma unroll
            for (int c = 0; c < 4; c++) {
                float x = (c == 0) ? q.x : (c == 1) ? q.y : (c == 2) ? q.z : q.w;
                unsigned u = __float_as_uint(x);
                if ((int)u >= 0) {
                    int bkt = (int)(u >> 20);
                    if (bkt > T) partial += x;
                    else if (bkt == T && fits) { int pb = atomicAdd(&s_cnt, 1); s_buf[pb] = x; }
                }
            }
        }
        __syncthreads();

        if (fits) {
            if (kr == cT) {
                for (int i = t; i < cT; i += 1024) partial += s_buf[i];
            } else {
                // radix refinement on the gathered bucket (smem resident)
                s_hist[t] = 0;
                __syncthreads();
                for (int i = t; i < cT; i += 1024)
                    atomicAdd(&s_hist[(__float_as_uint(s_buf[i]) >> 10) & 1023], 1);
                __syncthreads();
                select1024(s_hist, kr, t, lane, wid, s_w, &sT, &sKr);
                const int T2 = sT; kr = sKr;
                __syncthreads();
                s_hist[t] = 0;
                __syncthreads();
                for (int i = t; i < cT; i += 1024) {
                    unsigned u = __float_as_uint(s_buf[i]);
                    if (((u >> 10) & 1023) == (unsigned)T2) atomicAdd(&s_hist[u & 1023], 1);
                }
                __syncthreads();
                select1024(s_hist, kr, t, lane, wid, s_w, &sT, &sKr);
                const unsigned thrbits = ((unsigned)T << 20) | ((unsigned)T2 << 10) | (unsigned)sT;
                const int krf = sKr;
                __syncthreads();
                for (int i = t; i < cT; i += 1024) {
                    float x = s_buf[i];
                    if (__float_as_uint(x) > thrbits) partial += x;
                }
                if (t == 0) s_extra = (float)krf * __uint_as_float(thrbits);
            }
        } else {
            // rare fallback: refine via global rescans, then exact sum
            s_hist[t] = 0;
            __syncthreads();
            for (int i = t; i < Na; i += 1024) {
                unsigned u = __float_as_uint(g_bce[off + i]);
                if ((int)u >= 0 && (int)(u >> 20) == T)
                    atomicAdd(&s_hist[(u >> 10) & 1023], 1);
            }
            __syncthreads();
            select1024(s_hist, kr, t, lane, wid, s_w, &sT, &sKr);
            const int T2 = sT; kr = sKr;
            __syncthreads();
            s_hist[t] = 0;
            __syncthreads();
            const unsigned top22 = ((unsigned)T << 10) | (unsigned)T2;
            for (int i = t; i < Na; i += 1024) {
                unsigned u = __float_as_uint(g_bce[off + i]);
                if ((int)u >= 0 && (u >> 10) == top22)
                    atomicAdd(&s_hist[u & 1023], 1);
            }
            __syncthreads();
            select1024(s_hist, kr, t, lane, wid, s_w, &sT, &sKr);
            const unsigned thrbits = ((unsigned)T << 20) | ((unsigned)T2 << 10) | (unsigned)sT;
            const int krf = sKr;
            __syncthreads();
            partial = 0.f;
            for (int i = t; i < Na; i += 1024) {
                float x = g_bce[off + i];
                unsigned u = __float_as_uint(x);
                if ((int)u >= 0 && u > thrbits) partial += x;
            }
            if (t == 0) s_extra = (float)krf * __uint_as_float(thrbits);
        }

        // --- block reduce of partial ---
        #pragma unroll
        for (int o = 16; o; o >>= 1) partial += __shfl_down_sync(~0u, partial, o);
        if (lane == 0) s_fw[wid] = partial;
        __syncthreads();
        if (t == 0) {
            float s = s_extra;
            #pragma unroll
            for (int i = 0; i < 32; i++) s += s_fw[i];
            o_val = g_posbce[idx] / (float)npos + s / (float)k;
        }
    }

    // --- cleanup for next replay + accumulate totals ---
    hrow[t] = 0;
    hrow[t + 1024] = 0;
    if (t == 0) {
        float c = 0.f, l = 0.f;
        if (npos > 0) {
            c = g_cls[idx] / (float)npos;
            l = g_loc[idx] / (4.0f * (float)npos);
        }
        g_npos[idx] = 0; g_navail[idx] = 0;
        g_posbce[idx] = 0.f; g_cls[idx] = 0.f; g_loc[idx] = 0.f;
        atomicAdd(&g_tot[0], o_val);
        atomicAdd(&g_tot[1], c);
        atomicAdd(&g_tot[2], l);
        __threadfence();
        int done = atomicAdd(&g_done, 1);
        if (done == 191) {
            __threadfence();
            float oo = g_tot[0] / (float)NBATCH;
            float cc = g_tot[1] / (float)NBATCH;
            float ll = g_tot[2] / (float)NBATCH;
            out[0] = oo; out[1] = cc; out[2] = ll; out[3] = oo + cc + ll;
            g_tot[0] = 0.f; g_tot[1] = 0.f; g_tot[2] = 0.f;
            g_done = 0;
        }
    }
}

extern "C" void kernel_launch(void* const* d_in, const int* in_sizes, int n_in,
                              void* d_out, int out_size)
{
    const float* p0 = (const float*)d_in[0];
    const float* p1 = (const float*)d_in[1];
    const float* p2 = (const float*)d_in[2];
    const float* a0 = (const float*)d_in[3];
    const float* a1 = (const float*)d_in[4];
    const float* a2 = (const float*)d_in[5];
    const float* tb = (const float*)d_in[6];
    const int*   tl = (const int*)  d_in[7];

    dim3 gA(NBa0 + NBa1 + NBa2, NBATCH);
    k_phaseA<<<gA, 256>>>(p0, p1, p2, a0, a1, a2, tb, tl);
    k_phaseB<<<192, 1024>>>((float*)d_out);
}

// round 7
// speedup vs baseline: 1.9315x; 1.0968x over previous
#include <cuda_runtime.h>

#define NG 16
#define NBATCH 64
#define INV224 (1.0f / 224.0f)

static const int NA0 = 37632;   // 3*112*112
static const int NA1 = 9408;    // 3*56*56
static const int NA2 = 2352;    // 3*28*28
// phaseA blocks process 1024 anchors each (256 thr x 4)
static const int NBa0 = 37, NBa1 = 10, NBa2 = 3;

// scratch: [scale][image][anchor]
static __device__ float g_bce[3161088];
// per-(img,scale) 2048-bin histograms of float-bits>>20 (phaseB re-zeroes)
static __device__ int   g_hist[192 * 2048];
static __device__ float g_posbce[192];
static __device__ float g_cls[192];
static __device__ float g_loc[192];
static __device__ int   g_npos[192];
static __device__ int   g_navail[192];
static __device__ float g_tot[3];
static __device__ int   g_done;

// ---------------- Phase A ----------------

template<int H, int NA, int ACCB, long SCRB>
__device__ __forceinline__ void phaseA_impl(const float* __restrict__ p,
                                            const float* __restrict__ anchors,
                                            const float* __restrict__ tb,
                                            const int*   __restrict__ tl,
                                            int bs, int b)
{
    constexpr int HH = H * H;
    __shared__ float stb[NG * 4];
    __shared__ float sarea[NG];
    __shared__ int   stl[NG];
    __shared__ float s_pb, s_cl, s_lo;
    __shared__ int   s_np, s_nv;
    __shared__ int   s_h[2048];          // block-local histogram

    const int t = threadIdx.x;
    if (t < NG * 4) stb[t] = tb[b * NG * 4 + t] * INV224;
    if (t < NG)     stl[t] = tl[b * NG + t];
    if (t == 0) { s_pb = 0.f; s_cl = 0.f; s_lo = 0.f; s_np = 0; s_nv = 0; }
    #pragma unroll
    for (int i = 0; i < 8; i++) s_h[t + i * 256] = 0;
    __syncthreads();
    if (t < NG) sarea[t] = (stb[t * 4 + 2] - stb[t * 4 + 0]) * (stb[t * 4 + 3] - stb[t * 4 + 1]);
    __syncthreads();

    const int n0 = bs * 1024 + t;

    float ax1[4], ay1[4], ax2[4], ay2[4], area[4];
    bool  act[4];
    #pragma unroll
    for (int j = 0; j < 4; j++) {
        const int n = n0 + j * 256;
        act[j] = (n < NA);
        if (act[j]) {
            const float4 a4 = ((const float4*)anchors)[n];
            ax1[j] = a4.x * INV224; ay1[j] = a4.y * INV224;
            ax2[j] = a4.z * INV224; ay2[j] = a4.w * INV224;
            area[j] = (ax2[j] - ax1[j]) * (ay2[j] - ay1[j]);
        } else {
            ax1[j] = 0.f; ay1[j] = 0.f; ax2[j] = 0.f; ay2[j] = 0.f; area[j] = 0.f;
        }
    }

    float bestI[4], bestD[4]; int bi[4];
    #pragma unroll
    for (int j = 0; j < 4; j++) { bestI[j] = -1.f; bestD[j] = 1.f; bi[j] = 0; }

    // 16-box IoU loop: smem loads amortized across the 4 anchors
    #pragma unroll
    for (int g = 0; g < NG; g++) {
        const float bx1 = stb[g * 4 + 0], by1 = stb[g * 4 + 1];
        const float bx2 = stb[g * 4 + 2], by2 = stb[g * 4 + 3];
        const float ba  = sarea[g];
        #pragma unroll
        for (int j = 0; j < 4; j++) {
            float lx = fmaxf(ax1[j], bx1), ly = fmaxf(ay1[j], by1);
            float rx = fminf(ax2[j], bx2), ry = fminf(ay2[j], by2);
            float iw = fmaxf(rx - lx, 0.f), ih = fmaxf(ry - ly, 0.f);
            float inter = iw * ih;
            float den = area[j] + ba - inter + 1e-9f;
            if (inter * bestD[j] > bestI[j] * den) { bestI[j] = inter; bestD[j] = den; bi[j] = g; }
        }
    }

    int cnt_p = 0, cnt_n = 0;

    #pragma unroll
    for (int j = 0; j < 4; j++) {
        const int n = n0 + j * 256;
        if (act[j]) {
            const bool pos = bestI[j] >= 0.5f * bestD[j];
            const bool neg = bestI[j] <  0.4f * bestD[j];
            cnt_p += pos; cnt_n += neg;

            const int a = n / HH;
            const int rem = n - a * HH;
            const float* base = p + (((long)b * 3 + a) * 8) * (long)HH + rem;

            const float o = base[(long)4 * HH];
            const float bce = fmaxf(o, 0.f) - (pos ? o : 0.f) + __logf(1.0f + __expf(-fabsf(o)));

            g_bce[SCRB + (long)b * NA + n] = neg ? bce : -1.0f;

            if (neg)
                atomicAdd(&s_h[(int)(__float_as_uint(bce) >> 20)], 1);

            if (pos) {
                atomicAdd(&s_pb, bce);
                const int gi = bi[j];
                float mx1 = stb[gi * 4 + 0], my1 = stb[gi * 4 + 1];
                float mx2 = stb[gi * 4 + 2], my2 = stb[gi * 4 + 3];
                float gcx = 0.5f * (mx1 + mx2), gcy = 0.5f * (my1 + my2);
                float gw = mx2 - mx1, gh = my2 - my1;
                float aw = ax2[j] - ax1[j], ah = ay2[j] - ay1[j];
                float acx = 0.5f * (ax1[j] + ax2[j]), acy = 0.5f * (ay1[j] + ay2[j]);
                float e0 = __fdividef(gcx - acx, aw);
                float e1 = __fdividef(gcy - acy, ah);
                float e2 = __logf(__fdividef(gw, aw) + 1e-6f);
                float e3 = __logf(__fdividef(gh, ah) + 1e-6f);
                float d0 = base[0]            - e0;
                float d1 = base[(long)1 * HH] - e1;
                float d2 = base[(long)2 * HH] - e2;
                float d3 = base[(long)3 * HH] - e3;
                #define SL1_(d) (fabsf(d) < 1.f ? 0.5f * (d) * (d) : fabsf(d) - 0.5f)
                atomicAdd(&s_lo, SL1_(d0) + SL1_(d1) + SL1_(d2) + SL1_(d3));
                #undef SL1_
                float z0 = base[(long)5 * HH];
                float z1 = base[(long)6 * HH];
                float z2 = base[(long)7 * HH];
                float m = fmaxf(z0, fmaxf(z1, z2));
                float lse = m + __logf(__expf(z0 - m) + __expf(z1 - m) + __expf(z2 - m));
                int ml = stl[gi];
                float zl = (ml == 1) ? z0 : ((ml == 2) ? z1 : z2);
                atomicAdd(&s_cl, lse - zl);
            }
        }
    }

    // warp-level count reduction, one smem atomic per warp
    unsigned wp = __reduce_add_sync(0xffffffff, (unsigned)cnt_p);
    unsigned wn = __reduce_add_sync(0xffffffff, (unsigned)cnt_n);
    if ((t & 31) == 0) {
        if (wp) atomicAdd(&s_np, (int)wp);
        if (wn) atomicAdd(&s_nv, (int)wn);
    }
    __syncthreads();

    // flush block histogram (nonzero bins only) and block accumulators
    int* hrow = &g_hist[(ACCB + b) * 2048];
    #pragma unroll
    for (int i = 0; i < 8; i++) {
        int c = s_h[t + i * 256];
        if (c) atomicAdd(&hrow[t + i * 256], c);
    }
    if (t == 0) {
        const int acc = ACCB + b;
        if (s_np) {
            atomicAdd(&g_npos[acc],   s_np);
            atomicAdd(&g_posbce[acc], s_pb);
            atomicAdd(&g_cls[acc],    s_cl);
            atomicAdd(&g_loc[acc],    s_lo);
        }
        if (s_nv) atomicAdd(&g_navail[acc], s_nv);
    }
}

__global__ void __launch_bounds__(256) k_phaseA(const float* __restrict__ p0,
                                                const float* __restrict__ p1,
                                                const float* __restrict__ p2,
                                                const float* __restrict__ a0,
                                                const float* __restrict__ a1,
                                                const float* __restrict__ a2,
                                                const float* __restrict__ tb,
                                                const int*   __restrict__ tl)
{
    const int bx = blockIdx.x, b = blockIdx.y;
    if (bx < NBa0)             phaseA_impl<112, NA0, 0,   0L>(p0, a0, tb, tl, bx, b);
    else if (bx < NBa0 + NBa1) phaseA_impl<56,  NA1, 64,  2408448L>(p1, a1, tb, tl, bx - NBa0, b);
    else                       phaseA_impl<28,  NA2, 128, 3010560L>(p2, a2, tb, tl, bx - NBa0 - NBa1, b);
}

// ---------------- Phase B ----------------

__device__ __forceinline__ void select1024(const int* hist, int k, int t, int lane,
                                           int wid, int* s_w, int* sT, int* sKr)
{
    int c = hist[1023 - t];
    int v = c;
    #pragma unroll
    for (int o = 1; o < 32; o <<= 1) { int u = __shfl_up_sync(~0u, v, o); if (lane >= o) v += u; }
    if (lane == 31) s_w[wid] = v;
    __syncthreads();
    if (wid == 0) {
        int w = s_w[lane];
        #pragma unroll
        for (int o = 1; o < 32; o <<= 1) { int u = __shfl_up_sync(~0u, w, o); if (lane >= o) w += u; }
        s_w[lane] = w;
    }
    __syncthreads();
    int incl = v + (wid ? s_w[wid - 1] : 0);
    int excl = incl - c;
    if (excl < k && k <= incl) { *sT = 1023 - t; *sKr = k - excl; }
    __syncthreads();
}

__global__ void __launch_bounds__(1024) k_phaseB(float* __restrict__ out)
{
    const int idx = blockIdx.x;                 // 0..191
    const int scale = idx >> 6;
    const int b = idx & 63;
    const int Na   = (scale == 0) ? NA0 : ((scale == 1) ? NA1 : NA2);
    const long off = ((scale == 0) ? 0L : ((scale == 1) ? 2408448L : 3010560L)) + (long)b * Na;
    const int t = threadIdx.x, lane = t & 31, wid = t >> 5;
    const int npos = g_npos[idx];
    const int navail = g_navail[idx];

    __shared__ int   s_w[32];
    __shared__ float s_fw[32];
    __shared__ int   s_hist[1024];
    __shared__ float s_buf[4096];
    __shared__ int   s_cnt, sT, sKr;
    __shared__ float s_extra;

    int* hrow = &g_hist[idx * 2048];
    float partial = 0.f;
    float o_val = 0.f;
    const int k = min(3 * npos, navail);

    if (npos > 0 && navail > 0) {
        // --- level-1 select over 2048 bins (pairs from top), warp scans ---
        int c0 = hrow[2047 - 2 * t];
        int c1 = hrow[2046 - 2 * t];
        int v = c0 + c1;
        #pragma unroll
        for (int o = 1; o < 32; o <<= 1) { int u = __shfl_up_sync(~0u, v, o); if (lane >= o) v += u; }
        if (lane == 31) s_w[wid] = v;
        __syncthreads();
        if (wid == 0) {
            int w = s_w[lane];
            #pragma unroll
            for (int o = 1; o < 32; o <<= 1) { int u = __shfl_up_sync(~0u, w, o); if (lane >= o) w += u; }
            s_w[lane] = w;
        }
        if (t == 0) { s_cnt = 0; s_extra = 0.f; }
        __syncthreads();
        int incl = v + (wid ? s_w[wid - 1] : 0);
        int excl = incl - c0 - c1;
        if (excl < k && k <= incl) {
            if (excl + c0 >= k) { sT = 2047 - 2 * t; sKr = k - excl; }
            else                { sT = 2046 - 2 * t; sKr = k - excl - c0; }
        }
        __syncthreads();
        const int T = sT;
        int kr = sKr;
        const int cT = hrow[T];
        const bool fits = (cT <= 4096);

        // --- single float4 data scan: sum buckets > T, gather bucket T ---
        const float4* p4 = (const float4*)&g_bce[off];
        const int n4 = Na >> 2;
        for (int i = t; i < n4; i += 1024) {
            float4 q = p4[i];
            #pragma unroll
            for (int c = 0; c < 4; c++) {
                float x = (c == 0) ? q.x : (c == 1) ? q.y : (c == 2) ? q.z : q.w;
                unsigned u = __float_as_uint(x);
                if ((int)u >= 0) {
                    int bkt = (int)(u >> 20);
                    if (bkt > T) partial += x;
                    else if (bkt == T && fits) { int pb = atomicAdd(&s_cnt, 1); s_buf[pb] = x; }
                }
            }
        }
        __syncthreads();

        if (fits) {
            if (kr == cT) {
                for (int i = t; i < cT; i += 1024) partial += s_buf[i];
            } else {
                // radix refinement on the gathered bucket (smem resident)
                s_hist[t] = 0;
                __syncthreads();
                for (int i = t; i < cT; i += 1024)
                    atomicAdd(&s_hist[(__float_as_uint(s_buf[i]) >> 10) & 1023], 1);
                __syncthreads();
                select1024(s_hist, kr, t, lane, wid, s_w, &sT, &sKr);
                const int T2 = sT; kr = sKr;
                __syncthreads();
                s_hist[t] = 0;
                __syncthreads();
                for (int i = t; i < cT; i += 1024) {
                    unsigned u = __float_as_uint(s_buf[i]);
                    if (((u >> 10) & 1023) == (unsigned)T2) atomicAdd(&s_hist[u & 1023], 1);
                }
                __syncthreads();
                select1024(s_hist, kr, t, lane, wid, s_w, &sT, &sKr);
                const unsigned thrbits = ((unsigned)T << 20) | ((unsigned)T2 << 10) | (unsigned)sT;
                const int krf = sKr;
                __syncthreads();
                for (int i = t; i < cT; i += 1024) {
                    float x = s_buf[i];
                    if (__float_as_uint(x) > thrbits) partial += x;
                }
                if (t == 0) s_extra = (float)krf * __uint_as_float(thrbits);
            }
        } else {
            // rare fallback: refine via global rescans, then exact sum
            s_hist[t] = 0;
            __syncthreads();
            for (int i = t; i < Na; i += 1024) {
                unsigned u = __float_as_uint(g_bce[off + i]);
                if ((int)u >= 0 && (int)(u >> 20) == T)
                    atomicAdd(&s_hist[(u >> 10) & 1023], 1);
            }
            __syncthreads();
            select1024(s_hist, kr, t, lane, wid, s_w, &sT, &sKr);
            const int T2 = sT; kr = sKr;
            __syncthreads();
            s_hist[t] = 0;
            __syncthreads();
            const unsigned top22 = ((unsigned)T << 10) | (unsigned)T2;
            for (int i = t; i < Na; i += 1024) {
                unsigned u = __float_as_uint(g_bce[off + i]);
                if ((int)u >= 0 && (u >> 10) == top22)
                    atomicAdd(&s_hist[u & 1023], 1);
            }
            __syncthreads();
            select1024(s_hist, kr, t, lane, wid, s_w, &sT, &sKr);
            const unsigned thrbits = ((unsigned)T << 20) | ((unsigned)T2 << 10) | (unsigned)sT;
            const int krf = sKr;
            __syncthreads();
            partial = 0.f;
            for (int i = t; i < Na; i += 1024) {
                float x = g_bce[off + i];
                unsigned u = __float_as_uint(x);
                if ((int)u >= 0 && u > thrbits) partial += x;
            }
            if (t == 0) s_extra = (float)krf * __uint_as_float(thrbits);
        }

        // --- block reduce of partial ---
        #pragma unroll
        for (int o = 16; o; o >>= 1) partial += __shfl_down_sync(~0u, partial, o);
        if (lane == 0) s_fw[wid] = partial;
        __syncthreads();
        if (t == 0) {
            float s = s_extra;
            #pragma unroll
            for (int i = 0; i < 32; i++) s += s_fw[i];
            o_val = g_posbce[idx] / (float)npos + s / (float)k;
        }
    }

    // --- cleanup for next replay + accumulate totals ---
    hrow[t] = 0;
    hrow[t + 1024] = 0;
    if (t == 0) {
        float c = 0.f, l = 0.f;
        if (npos > 0) {
            c = g_cls[idx] / (float)npos;
            l = g_loc[idx] / (4.0f * (float)npos);
        }
        g_npos[idx] = 0; g_navail[idx] = 0;
        g_posbce[idx] = 0.f; g_cls[idx] = 0.f; g_loc[idx] = 0.f;
        atomicAdd(&g_tot[0], o_val);
        atomicAdd(&g_tot[1], c);
        atomicAdd(&g_tot[2], l);
        __threadfence();
        int done = atomicAdd(&g_done, 1);
        if (done == 191) {
            __threadfence();
            float oo = g_tot[0] / (float)NBATCH;
            float cc = g_tot[1] / (float)NBATCH;
            float ll = g_tot[2] / (float)NBATCH;
            out[0] = oo; out[1] = cc; out[2] = ll; out[3] = oo + cc + ll;
            g_tot[0] = 0.f; g_tot[1] = 0.f; g_tot[2] = 0.f;
            g_done = 0;
        }
    }
}

extern "C" void kernel_launch(void* const* d_in, const int* in_sizes, int n_in,
                              void* d_out, int out_size)
{
    const float* p0 = (const float*)d_in[0];
    const float* p1 = (const float*)d_in[1];
    const float* p2 = (const float*)d_in[2];
    const float* a0 = (const float*)d_in[3];
    const float* a1 = (const float*)d_in[4];
    const float* a2 = (const float*)d_in[5];
    const float* tb = (const float*)d_in[6];
    const int*   tl = (const int*)  d_in[7];

    dim3 gA(NBa0 + NBa1 + NBa2, NBATCH);
    k_phaseA<<<gA, 256>>>(p0, p1, p2, a0, a1, a2, tb, tl);
    k_phaseB<<<192, 1024>>>((float*)d_out);
}

// round 8
// speedup vs baseline: 2.2996x; 1.1906x over previous
#include <cuda_runtime.h>

#define NG 16
#define NBATCH 64
#define INV224 (1.0f / 224.0f)

static const int NA0 = 37632;   // 3*112*112
static const int NA1 = 9408;    // 3*56*56
static const int NA2 = 2352;    // 3*28*28
// scale0: 42 blocks of 8 rows (112 cols); scales 1/2: generic 1024-anchor blocks
static const int NB0S = 42, NBa1 = 10, NBa2 = 3;

// scratch: [scale][image][anchor]
static __device__ float g_bce[3161088];
static __device__ int   g_hist[192 * 2048];
static __device__ float g_posbce[192];
static __device__ float g_cls[192];
static __device__ float g_loc[192];
static __device__ int   g_npos[192];
static __device__ int   g_navail[192];
static __device__ float g_tot[3];
static __device__ int   g_done;

// ---------------- Phase A: shared epilogue helpers ----------------

__device__ __forceinline__ void flush_block(int* s_h, int* hrow, int acc,
                                            int s_np, int s_nv,
                                            float s_pb, float s_cl, float s_lo, int t)
{
    #pragma unroll
    for (int i = 0; i < 8; i++) {
        int c = s_h[t + i * 256];
        if (c) atomicAdd(&hrow[t + i * 256], c);
    }
    if (t == 0) {
        if (s_np) {
            atomicAdd(&g_npos[acc],   s_np);
            atomicAdd(&g_posbce[acc], s_pb);
            atomicAdd(&g_cls[acc],    s_cl);
            atomicAdd(&g_loc[acc],    s_lo);
        }
        if (s_nv) atomicAdd(&g_navail[acc], s_nv);
    }
}

// ---------------- Phase A: specialized scale-0 path (separable IoU) ----------------

__device__ void scale0_path(const float* __restrict__ p,
                            const float* __restrict__ anchors,
                            const float* __restrict__ tb,
                            const int*   __restrict__ tl,
                            int bi, int b, int* s_h)
{
    constexpr int HH = 112 * 112;
    __shared__ float  s_iwS[16 * 112];     // iw(x,g) * invS(g)
    __shared__ float4 s_ih4[32];           // ih[g][8 rows] as 2 float4 per g
    __shared__ float  s_invS[16];
    __shared__ float  stb0[64];
    __shared__ float  sarea0[16];
    __shared__ int    stl0[16];
    __shared__ float  z_pb, z_cl, z_lo;
    __shared__ int    z_np, z_nv;

    const int t = threadIdx.x;
    const int a = bi / 14;                 // anchor-size index (8 rows * 14 = 112)
    const int row0 = bi * 8;               // global row in [0, 336)
    const int y0 = row0 - a * 112;

    if (t < 64) stb0[t] = tb[b * 64 + t] * INV224;
    if (t < 16) stl0[t] = tl[b * 16 + t];
    if (t == 0) { z_pb = 0.f; z_cl = 0.f; z_lo = 0.f; z_np = 0; z_nv = 0; }
    #pragma unroll
    for (int i = 0; i < 8; i++) s_h[t + i * 256] = 0;
    __syncthreads();

    if (t < 16) {
        float s = (stb0[t * 4 + 2] - stb0[t * 4 + 0]) * (stb0[t * 4 + 3] - stb0[t * 4 + 1]);
        sarea0[t] = s;
        const float4 a4 = ((const float4*)anchors)[a * HH];
        float aw = (a4.z - a4.x) * INV224, ah = (a4.w - a4.y) * INV224;
        s_invS[t] = __fdividef(1.0f, aw * ah + s);
    }
    __syncthreads();

    // iwS table: 16 boxes x 112 x-positions
    for (int e = t; e < 16 * 112; e += 256) {
        int g = e / 112, x = e - g * 112;
        const float4 a4 = ((const float4*)anchors)[a * HH + x];
        float ax1 = a4.x * INV224, ax2 = a4.z * INV224;
        float lx = fmaxf(ax1, stb0[g * 4 + 0]);
        float rx = fminf(ax2, stb0[g * 4 + 2]);
        s_iwS[e] = fmaxf(rx - lx, 0.f) * s_invS[g];
    }
    // ih table: 16 boxes x 8 rows (layout [g][row])
    if (t < 128) {
        int g = t >> 3, r = t & 7;
        const float4 a4 = ((const float4*)anchors)[a * HH + (y0 + r) * 112];
        float ay1 = a4.y * INV224, ay2 = a4.w * INV224;
        float ly = fmaxf(ay1, stb0[g * 4 + 1]);
        float ry = fminf(ay2, stb0[g * 4 + 3]);
        ((float*)s_ih4)[t] = fmaxf(ry - ly, 0.f);
    }
    __syncthreads();

    const bool active = t < 224;
    const int x  = active ? (t % 112) : 0;
    const int rg = active ? (t / 112) : 0;    // row group 0/1 (4 rows each)

    float best0 = 0.f, best1 = 0.f, best2 = 0.f, best3 = 0.f;
    if (active) {
        #pragma unroll
        for (int g = 0; g < 16; g++) {
            const float iwS = s_iwS[g * 112 + x];
            const float4 ih = s_ih4[g * 2 + rg];
            best0 = fmaxf(best0, iwS * ih.x);
            best1 = fmaxf(best1, iwS * ih.y);
            best2 = fmaxf(best2, iwS * ih.z);
            best3 = fmaxf(best3, iwS * ih.w);
        }
    }

    int cnt_p = 0, cnt_n = 0;
    if (active) {
        float bests[4] = { best0, best1, best2, best3 };
        #pragma unroll
        for (int j = 0; j < 4; j++) {
            const float bj = bests[j];
            const bool pos = 3.0f * bj >= 1.0f;
            const bool neg = 3.5f * bj <  1.0f;
            cnt_p += pos; cnt_n += neg;

            const int grow = row0 + rg * 4 + j;
            const int y = grow - a * 112;
            const int rem = y * 112 + x;
            const int n = grow * 112 + x;
            const float* base = p + (((long)b * 3 + a) * 8) * (long)HH + rem;

            const float o = base[(long)4 * HH];
            const float bce = fmaxf(o, 0.f) - (pos ? o : 0.f) + __logf(1.0f + __expf(-fabsf(o)));

            g_bce[(long)b * NA0 + n] = neg ? bce : -1.0f;
            if (neg) atomicAdd(&s_h[(int)(__float_as_uint(bce) >> 20)], 1);

            if (pos) {
                // recompute argmax g (first max) for this anchor
                int gi = 0; float bb = -1.f;
                const float4* ihrow = &s_ih4[rg];
                #pragma unroll
                for (int g = 0; g < 16; g++) {
                    const float4 ih = ihrow[g * 2];
                    float ihj = (j == 0) ? ih.x : (j == 1) ? ih.y : (j == 2) ? ih.z : ih.w;
                    float sc = s_iwS[g * 112 + x] * ihj;
                    if (sc > bb) { bb = sc; gi = g; }
                }
                atomicAdd(&z_pb, bce);
                const float4 a4 = ((const float4*)anchors)[n];
                float ax1 = a4.x * INV224, ay1 = a4.y * INV224;
                float ax2 = a4.z * INV224, ay2 = a4.w * INV224;
                float aw = ax2 - ax1, ah = ay2 - ay1;
                float mx1 = stb0[gi * 4 + 0], my1 = stb0[gi * 4 + 1];
                float mx2 = stb0[gi * 4 + 2], my2 = stb0[gi * 4 + 3];
                float gcx = 0.5f * (mx1 + mx2), gcy = 0.5f * (my1 + my2);
                float gw = mx2 - mx1, gh = my2 - my1;
                float acx = 0.5f * (ax1 + ax2), acy = 0.5f * (ay1 + ay2);
                float e0 = __fdividef(gcx - acx, aw);
                float e1 = __fdividef(gcy - acy, ah);
                float e2 = __logf(__fdividef(gw, aw) + 1e-6f);
                float e3 = __logf(__fdividef(gh, ah) + 1e-6f);
                float d0 = base[0]            - e0;
                float d1 = base[(long)1 * HH] - e1;
                float d2 = base[(long)2 * HH] - e2;
                float d3 = base[(long)3 * HH] - e3;
                #define SL1_(d) (fabsf(d) < 1.f ? 0.5f * (d) * (d) : fabsf(d) - 0.5f)
                atomicAdd(&z_lo, SL1_(d0) + SL1_(d1) + SL1_(d2) + SL1_(d3));
                #undef SL1_
                float zv0 = base[(long)5 * HH];
                float zv1 = base[(long)6 * HH];
                float zv2 = base[(long)7 * HH];
                float m = fmaxf(zv0, fmaxf(zv1, zv2));
                float lse = m + __logf(__expf(zv0 - m) + __expf(zv1 - m) + __expf(zv2 - m));
                int ml = stl0[gi];
                float zl = (ml == 1) ? zv0 : ((ml == 2) ? zv1 : zv2);
                atomicAdd(&z_cl, lse - zl);
            }
        }
    }

    unsigned wp = __reduce_add_sync(0xffffffff, (unsigned)cnt_p);
    unsigned wn = __reduce_add_sync(0xffffffff, (unsigned)cnt_n);
    if ((t & 31) == 0) {
        if (wp) atomicAdd(&z_np, (int)wp);
        if (wn) atomicAdd(&z_nv, (int)wn);
    }
    __syncthreads();
    flush_block(s_h, &g_hist[b * 2048], b, z_np, z_nv, z_pb, z_cl, z_lo, t);
}

// ---------------- Phase A: generic path (scales 1,2) ----------------

template<int H, int NA, int ACCB, long SCRB>
__device__ __forceinline__ void phaseA_impl(const float* __restrict__ p,
                                            const float* __restrict__ anchors,
                                            const float* __restrict__ tb,
                                            const int*   __restrict__ tl,
                                            int bs, int b, int* s_h)
{
    constexpr int HH = H * H;
    __shared__ float stb[NG * 4];
    __shared__ float sarea[NG];
    __shared__ int   stl[NG];
    __shared__ float s_pb, s_cl, s_lo;
    __shared__ int   s_np, s_nv;

    const int t = threadIdx.x;
    if (t < NG * 4) stb[t] = tb[b * NG * 4 + t] * INV224;
    if (t < NG)     stl[t] = tl[b * NG + t];
    if (t == 0) { s_pb = 0.f; s_cl = 0.f; s_lo = 0.f; s_np = 0; s_nv = 0; }
    #pragma unroll
    for (int i = 0; i < 8; i++) s_h[t + i * 256] = 0;
    __syncthreads();
    if (t < NG) sarea[t] = (stb[t * 4 + 2] - stb[t * 4 + 0]) * (stb[t * 4 + 3] - stb[t * 4 + 1]);
    __syncthreads();

    const int n0 = bs * 1024 + t;

    float ax1[4], ay1[4], ax2[4], ay2[4], area[4];
    bool  act[4];
    #pragma unroll
    for (int j = 0; j < 4; j++) {
        const int n = n0 + j * 256;
        act[j] = (n < NA);
        if (act[j]) {
            const float4 a4 = ((const float4*)anchors)[n];
            ax1[j] = a4.x * INV224; ay1[j] = a4.y * INV224;
            ax2[j] = a4.z * INV224; ay2[j] = a4.w * INV224;
            area[j] = (ax2[j] - ax1[j]) * (ay2[j] - ay1[j]);
        } else {
            ax1[j] = 0.f; ay1[j] = 0.f; ax2[j] = 0.f; ay2[j] = 0.f; area[j] = 0.f;
        }
    }

    float bestI[4], bestD[4]; int bi[4];
    #pragma unroll
    for (int j = 0; j < 4; j++) { bestI[j] = -1.f; bestD[j] = 1.f; bi[j] = 0; }

    #pragma unroll
    for (int g = 0; g < NG; g++) {
        const float bx1 = stb[g * 4 + 0], by1 = stb[g * 4 + 1];
        const float bx2 = stb[g * 4 + 2], by2 = stb[g * 4 + 3];
        const float ba  = sarea[g];
        #pragma unroll
        for (int j = 0; j < 4; j++) {
            float lx = fmaxf(ax1[j], bx1), ly = fmaxf(ay1[j], by1);
            float rx = fminf(ax2[j], bx2), ry = fminf(ay2[j], by2);
            float iw = fmaxf(rx - lx, 0.f), ih = fmaxf(ry - ly, 0.f);
            float inter = iw * ih;
            float den = area[j] + ba - inter + 1e-9f;
            if (inter * bestD[j] > bestI[j] * den) { bestI[j] = inter; bestD[j] = den; bi[j] = g; }
        }
    }

    int cnt_p = 0, cnt_n = 0;

    #pragma unroll
    for (int j = 0; j < 4; j++) {
        const int n = n0 + j * 256;
        if (act[j]) {
            const bool pos = bestI[j] >= 0.5f * bestD[j];
            const bool neg = bestI[j] <  0.4f * bestD[j];
            cnt_p += pos; cnt_n += neg;

            const int a = n / HH;
            const int rem = n - a * HH;
            const float* base = p + (((long)b * 3 + a) * 8) * (long)HH + rem;

            const float o = base[(long)4 * HH];
            const float bce = fmaxf(o, 0.f) - (pos ? o : 0.f) + __logf(1.0f + __expf(-fabsf(o)));

            g_bce[SCRB + (long)b * NA + n] = neg ? bce : -1.0f;

            if (neg) atomicAdd(&s_h[(int)(__float_as_uint(bce) >> 20)], 1);

            if (pos) {
                atomicAdd(&s_pb, bce);
                const int gi = bi[j];
                float mx1 = stb[gi * 4 + 0], my1 = stb[gi * 4 + 1];
                float mx2 = stb[gi * 4 + 2], my2 = stb[gi * 4 + 3];
                float gcx = 0.5f * (mx1 + mx2), gcy = 0.5f * (my1 + my2);
                float gw = mx2 - mx1, gh = my2 - my1;
                float aw = ax2[j] - ax1[j], ah = ay2[j] - ay1[j];
                float acx = 0.5f * (ax1[j] + ax2[j]), acy = 0.5f * (ay1[j] + ay2[j]);
                float e0 = __fdividef(gcx - acx, aw);
                float e1 = __fdividef(gcy - acy, ah);
                float e2 = __logf(__fdividef(gw, aw) + 1e-6f);
                float e3 = __logf(__fdividef(gh, ah) + 1e-6f);
                float d0 = base[0]            - e0;
                float d1 = base[(long)1 * HH] - e1;
                float d2 = base[(long)2 * HH] - e2;
                float d3 = base[(long)3 * HH] - e3;
                #define SL1_(d) (fabsf(d) < 1.f ? 0.5f * (d) * (d) : fabsf(d) - 0.5f)
                atomicAdd(&s_lo, SL1_(d0) + SL1_(d1) + SL1_(d2) + SL1_(d3));
                #undef SL1_
                float z0 = base[(long)5 * HH];
                float z1 = base[(long)6 * HH];
                float z2 = base[(long)7 * HH];
                float m = fmaxf(z0, fmaxf(z1, z2));
                float lse = m + __logf(__expf(z0 - m) + __expf(z1 - m) + __expf(z2 - m));
                int ml = stl[gi];
                float zl = (ml == 1) ? z0 : ((ml == 2) ? z1 : z2);
                atomicAdd(&s_cl, lse - zl);
            }
        }
    }

    unsigned wp = __reduce_add_sync(0xffffffff, (unsigned)cnt_p);
    unsigned wn = __reduce_add_sync(0xffffffff, (unsigned)cnt_n);
    if ((t & 31) == 0) {
        if (wp) atomicAdd(&s_np, (int)wp);
        if (wn) atomicAdd(&s_nv, (int)wn);
    }
    __syncthreads();
    flush_block(s_h, &g_hist[(ACCB + b) * 2048], ACCB + b, s_np, s_nv, s_pb, s_cl, s_lo, t);
}

__global__ void __launch_bounds__(256) k_phaseA(const float* __restrict__ p0,
                                                const float* __restrict__ p1,
                                                const float* __restrict__ p2,
                                                const float* __restrict__ a0,
                                                const float* __restrict__ a1,
                                                const float* __restrict__ a2,
                                                const float* __restrict__ tb,
                                                const int*   __restrict__ tl)
{
    __shared__ int s_h[2048];
    const int bx = blockIdx.x, b = blockIdx.y;
    if (bx < NB0S)             scale0_path(p0, a0, tb, tl, bx, b, s_h);
    else if (bx < NB0S + NBa1) phaseA_impl<56, NA1, 64,  2408448L>(p1, a1, tb, tl, bx - NB0S, b, s_h);
    else                       phaseA_impl<28, NA2, 128, 3010560L>(p2, a2, tb, tl, bx - NB0S - NBa1, b, s_h);
}

// ---------------- Phase B ----------------

__device__ __forceinline__ void select1024(const int* hist, int k, int t, int lane,
                                           int wid, int* s_w, int* sT, int* sKr)
{
    int c = hist[1023 - t];
    int v = c;
    #pragma unroll
    for (int o = 1; o < 32; o <<= 1) { int u = __shfl_up_sync(~0u, v, o); if (lane >= o) v += u; }
    if (lane == 31) s_w[wid] = v;
    __syncthreads();
    if (wid == 0) {
        int w = s_w[lane];
        #pragma unroll
        for (int o = 1; o < 32; o <<= 1) { int u = __shfl_up_sync(~0u, w, o); if (lane >= o) w += u; }
        s_w[lane] = w;
    }
    __syncthreads();
    int incl = v + (wid ? s_w[wid - 1] : 0);
    int excl = incl - c;
    if (excl < k && k <= incl) { *sT = 1023 - t; *sKr = k - excl; }
    __syncthreads();
}

__global__ void __launch_bounds__(1024) k_phaseB(float* __restrict__ out)
{
    const int idx = blockIdx.x;                 // 0..191
    const int scale = idx >> 6;
    const int b = idx & 63;
    const int Na   = (scale == 0) ? NA0 : ((scale == 1) ? NA1 : NA2);
    const long off = ((scale == 0) ? 0L : ((scale == 1) ? 2408448L : 3010560L)) + (long)b * Na;
    const int t = threadIdx.x, lane = t & 31, wid = t >> 5;
    const int npos = g_npos[idx];
    const int navail = g_navail[idx];

    __shared__ int   s_w[32];
    __shared__ float s_fw[32];
    __shared__ int   s_hist[1024];
    __shared__ float s_buf[4096];
    __shared__ int   s_cnt, sT, sKr;
    __shared__ float s_extra;

    int* hrow = &g_hist[idx * 2048];
    float partial = 0.f;
    float o_val = 0.f;
    const int k = min(3 * npos, navail);

    if (npos > 0 && navail > 0) {
        int c0 = hrow[2047 - 2 * t];
        int c1 = hrow[2046 - 2 * t];
        int v = c0 + c1;
        #pragma unroll
        for (int o = 1; o < 32; o <<= 1) { int u = __shfl_up_sync(~0u, v, o); if (lane >= o) v += u; }
        if (lane == 31) s_w[wid] = v;
        __syncthreads();
        if (wid == 0) {
            int w = s_w[lane];
            #pragma unroll
            for (int o = 1; o < 32; o <<= 1) { int u = __shfl_up_sync(~0u, w, o); if (lane >= o) w += u; }
            s_w[lane] = w;
        }
        if (t == 0) { s_cnt = 0; s_extra = 0.f; }
        __syncthreads();
        int incl = v + (wid ? s_w[wid - 1] : 0);
        int excl = incl - c0 - c1;
        if (excl < k && k <= incl) {
            if (excl + c0 >= k) { sT = 2047 - 2 * t; sKr = k - excl; }
            else                { sT = 2046 - 2 * t; sKr = k - excl - c0; }
        }
        __syncthreads();
        const int T = sT;
        int kr = sKr;
        const int cT = hrow[T];
        const bool fits = (cT <= 4096);

        const float4* p4 = (const float4*)&g_bce[off];
        const int n4 = Na >> 2;
        for (int i = t; i < n4; i += 1024) {
            float4 q = p4[i];
            #pragma unroll
            for (int c = 0; c < 4; c++) {
                float x = (c == 0) ? q.x : (c == 1) ? q.y : (c == 2) ? q.z : q.w;
                unsigned u = __float_as_uint(x);
                if ((int)u >= 0) {
                    int bkt = (int)(u >> 20);
                    if (bkt > T) partial += x;
                    else if (bkt == T && fits) { int pb = atomicAdd(&s_cnt, 1); s_buf[pb] = x; }
                }
            }
        }
        __syncthreads();

        if (fits) {
            if (kr == cT) {
                for (int i = t; i < cT; i += 1024) partial += s_buf[i];
            } else {
                s_hist[t] = 0;
                __syncthreads();
                for (int i = t; i < cT; i += 1024)
                    atomicAdd(&s_hist[(__float_as_uint(s_buf[i]) >> 10) & 1023], 1);
                __syncthreads();
                select1024(s_hist, kr, t, lane, wid, s_w, &sT, &sKr);
                const int T2 = sT; kr = sKr;
                __syncthreads();
                s_hist[t] = 0;
                __syncthreads();
                for (int i = t; i < cT; i += 1024) {
                    unsigned u = __float_as_uint(s_buf[i]);
                    if (((u >> 10) & 1023) == (unsigned)T2) atomicAdd(&s_hist[u & 1023], 1);
                }
                __syncthreads();
                select1024(s_hist, kr, t, lane, wid, s_w, &sT, &sKr);
                const unsigned thrbits = ((unsigned)T << 20) | ((unsigned)T2 << 10) | (unsigned)sT;
                const int krf = sKr;
                __syncthreads();
                for (int i = t; i < cT; i += 1024) {
                    float x = s_buf[i];
                    if (__float_as_uint(x) > thrbits) partial += x;
                }
                if (t == 0) s_extra = (float)krf * __uint_as_float(thrbits);
            }
        } else {
            s_hist[t] = 0;
            __syncthreads();
            for (int i = t; i < Na; i += 1024) {
                unsigned u = __float_as_uint(g_bce[off + i]);
                if ((int)u >= 0 && (int)(u >> 20) == T)
                    atomicAdd(&s_hist[(u >> 10) & 1023], 1);
            }
            __syncthreads();
            select1024(s_hist, kr, t, lane, wid, s_w, &sT, &sKr);
            const int T2 = sT; kr = sKr;
            __syncthreads();
            s_hist[t] = 0;
            __syncthreads();
            const unsigned top22 = ((unsigned)T << 10) | (unsigned)T2;
            for (int i = t; i < Na; i += 1024) {
                unsigned u = __float_as_uint(g_bce[off + i]);
                if ((int)u >= 0 && (u >> 10) == top22)
                    atomicAdd(&s_hist[u & 1023], 1);
            }
            __syncthreads();
            select1024(s_hist, kr, t, lane, wid, s_w, &sT, &sKr);
            const unsigned thrbits = ((unsigned)T << 20) | ((unsigned)T2 << 10) | (unsigned)sT;
            const int krf = sKr;
            __syncthreads();
            partial = 0.f;
            for (int i = t; i < Na; i += 1024) {
                float x = g_bce[off + i];
                unsigned u = __float_as_uint(x);
                if ((int)u >= 0 && u > thrbits) partial += x;
            }
            if (t == 0) s_extra = (float)krf * __uint_as_float(thrbits);
        }

        #pragma unroll
        for (int o = 16; o; o >>= 1) partial += __shfl_down_sync(~0u, partial, o);
        if (lane == 0) s_fw[wid] = partial;
        __syncthreads();
        if (t == 0) {
            float s = s_extra;
            #pragma unroll
            for (int i = 0; i < 32; i++) s += s_fw[i];
            o_val = g_posbce[idx] / (float)npos + s / (float)k;
        }
    }

    hrow[t] = 0;
    hrow[t + 1024] = 0;
    if (t == 0) {
        float c = 0.f, l = 0.f;
        if (npos > 0) {
            c = g_cls[idx] / (float)npos;
            l = g_loc[idx] / (4.0f * (float)npos);
        }
        g_npos[idx] = 0; g_navail[idx] = 0;
        g_posbce[idx] = 0.f; g_cls[idx] = 0.f; g_loc[idx] = 0.f;
        atomicAdd(&g_tot[0], o_val);
        atomicAdd(&g_tot[1], c);
        atomicAdd(&g_tot[2], l);
        __threadfence();
        int done = atomicAdd(&g_done, 1);
        if (done == 191) {
            __threadfence();
            float oo = g_tot[0] / (float)NBATCH;
            float cc = g_tot[1] / (float)NBATCH;
            float ll = g_tot[2] / (float)NBATCH;
            out[0] = oo; out[1] = cc; out[2] = ll; out[3] = oo + cc + ll;
            g_tot[0] = 0.f; g_tot[1] = 0.f; g_tot[2] = 0.f;
            g_done = 0;
        }
    }
}

extern "C" void kernel_launch(void* const* d_in, const int* in_sizes, int n_in,
                              void* d_out, int out_size)
{
    const float* p0 = (const float*)d_in[0];
    const float* p1 = (const float*)d_in[1];
    const float* p2 = (const float*)d_in[2];
    const float* a0 = (const float*)d_in[3];
    const float* a1 = (const float*)d_in[4];
    const float* a2 = (const float*)d_in[5];
    const float* tb = (const float*)d_in[6];
    const int*   tl = (const int*)  d_in[7];

    dim3 gA(NB0S + NBa1 + NBa2, NBATCH);
    k_phaseA<<<gA, 256>>>(p0, p1, p2, a0, a1, a2, tb, tl);
    k_phaseB<<<192, 1024>>>((float*)d_out);
}